// round 5
// baseline (speedup 1.0000x reference)
#include <cuda_runtime.h>
#include <cuda_bf16.h>
#include <cstdint>

#define FH 32
#define FW 88
#define PPC 2816
#define NCAM 6
#define NPIX 16896
#define DD 41
#define CC 64
#define CIN 256
#define NOUT 105
#define NOUTP 112
#define NVOX 16384
#define DPAD 44

#define BXX (-50.8f - 0.4f)
#define BYY (-50.8f - 0.4f)
#define BZZ (-10.0f)

typedef unsigned long long ull;

__device__ __align__(16) float g_depth[NPIX * DPAD];
__device__ __align__(16) float g_ctx[NPIX * CC];
__device__ __align__(16) float g_bev[2][NVOX * CC];   // 2 replicas vs contention

__device__ __forceinline__ ull ffma2(ull a, ull b, ull c) {
    ull d;
    asm("fma.rn.f32x2 %0, %1, %2, %3;" : "=l"(d) : "l"(a), "l"(b), "l"(c));
    return d;
}

__device__ __forceinline__ void red2(float* addr, float a, float b) {
    asm volatile("red.global.add.v2.f32 [%0], {%1,%2};"
                 :: "l"(addr), "f"(a), "f"(b) : "memory");
}

__device__ __forceinline__ void cp8(uint32_t s, const float* g) {
    asm volatile("cp.async.ca.shared.global [%0], [%1], 8;" :: "r"(s), "l"(g));
}
__device__ __forceinline__ uint32_t s2u(const void* p) {
    return (uint32_t)__cvta_generic_to_shared(p);
}

// ---------------------------------------------------------------- K0: zero bev
__global__ void k_zero() {
    int i = blockIdx.x * blockDim.x + threadIdx.x;   // 2048*256 threads
    reinterpret_cast<float4*>(g_bev)[i] = make_float4(0.f, 0.f, 0.f, 0.f);
}

// ---------------- K1: pipelined register-blocked GEMM (FFMA2) + softmax
#define KCH 16
#define XROW 136
#define XS_BYTES (KCH * XROW * 4)
#define WS_BYTES (KCH * NOUTP * 8)
#define STAGE_BYTES (XS_BYTES + WS_BYTES)
#define EPI_STRIDE 113
#define FEATS_SMEM (128 * EPI_STRIDE * 4)

__global__ void __launch_bounds__(256) k_feats(const float* __restrict__ x,
                                               const float* __restrict__ wd,
                                               const float* __restrict__ bd) {
    extern __shared__ char smem[];
    float (*epi)[EPI_STRIDE] = reinterpret_cast<float(*)[EPI_STRIDE]>(smem);

    const int tid = threadIdx.x;
    const int pg = tid & 15;
    const int og = tid >> 4;
    const int pix0 = blockIdx.x * 128;
    const int n = pix0 / PPC;
    const int p0 = pix0 - n * PPC;
    const float* xb = x + n * CIN * PPC + p0;

    const int pc0 = pg * 8 + 2 * (pg >> 2);

    int xk[4], xc[4];
#pragma unroll
    for (int r = 0; r < 4; ++r) {
        int i = tid + 256 * r;
        xk[r] = i >> 6;
        xc[r] = i & 63;
    }
    int wk[7], wo[7];
#pragma unroll
    for (int r = 0; r < 7; ++r) {
        int i = tid + 256 * r;
        wk[r] = i / NOUTP;
        wo[r] = i - wk[r] * NOUTP;
    }

    ull acc[7][4];
#pragma unroll
    for (int o = 0; o < 7; ++o)
#pragma unroll
        for (int j = 0; j < 4; ++j) acc[o][j] = 0ULL;

    {
        char* st = smem;
#pragma unroll
        for (int r = 0; r < 4; ++r) {
            int pc = 2 * xc[r] + 2 * (xc[r] >> 4);
            cp8(s2u(st + (xk[r] * XROW + pc) * 4), xb + xk[r] * PPC + 2 * xc[r]);
        }
        float2* wsd = reinterpret_cast<float2*>(st + XS_BYTES);
#pragma unroll
        for (int r = 0; r < 7; ++r) {
            float w = (wo[r] < NOUT) ? wd[wo[r] * CIN + wk[r]] : 0.f;
            wsd[wk[r] * NOUTP + wo[r]] = make_float2(w, w);
        }
        asm volatile("cp.async.commit_group;");
        asm volatile("cp.async.wait_group 0;");
        __syncthreads();
    }

    for (int kc = 0; kc < CIN; kc += KCH) {
        char* cur = smem + ((kc >> 4) & 1) * STAGE_BYTES;
        char* nxt = smem + (~(kc >> 4) & 1) * STAGE_BYTES;
        const bool more = (kc + KCH) < CIN;

        float wv[7];
        if (more) {
            const float* xn = xb + (kc + KCH) * PPC;
#pragma unroll
            for (int r = 0; r < 4; ++r) {
                int pc = 2 * xc[r] + 2 * (xc[r] >> 4);
                cp8(s2u(nxt + (xk[r] * XROW + pc) * 4), xn + xk[r] * PPC + 2 * xc[r]);
            }
#pragma unroll
            for (int r = 0; r < 7; ++r)
                wv[r] = (wo[r] < NOUT) ? wd[wo[r] * CIN + kc + KCH + wk[r]] : 0.f;
        }

        const float* xs = reinterpret_cast<const float*>(cur);
        const float2* wsd = reinterpret_cast<const float2*>(cur + XS_BYTES);
#pragma unroll
        for (int k = 0; k < KCH; ++k) {
            ull w2[7], x2[4];
            const float* xr = xs + k * XROW + pc0;
#pragma unroll
            for (int o = 0; o < 7; ++o)
                w2[o] = *reinterpret_cast<const ull*>(&wsd[k * NOUTP + og * 7 + o]);
#pragma unroll
            for (int j = 0; j < 4; ++j)
                x2[j] = *reinterpret_cast<const ull*>(xr + 2 * j);
#pragma unroll
            for (int o = 0; o < 7; ++o)
#pragma unroll
                for (int j = 0; j < 4; ++j)
                    acc[o][j] = ffma2(w2[o], x2[j], acc[o][j]);
        }

        if (more) {
            float2* wsn = reinterpret_cast<float2*>(nxt + XS_BYTES);
#pragma unroll
            for (int r = 0; r < 7; ++r)
                wsn[wk[r] * NOUTP + wo[r]] = make_float2(wv[r], wv[r]);
        }
        asm volatile("cp.async.commit_group;");
        asm volatile("cp.async.wait_group 0;");
        __syncthreads();
    }

#pragma unroll
    for (int o = 0; o < 7; ++o) {
        int out = og * 7 + o;
        if (out < NOUT) {
#pragma unroll
            for (int j = 0; j < 4; ++j) {
                float2 f = *reinterpret_cast<float2*>(&acc[o][j]);
                int p = pg * 8 + 2 * j;
                epi[p][out] = f.x;
                epi[p + 1][out] = f.y;
            }
        }
    }
    __syncthreads();

    if (tid < 128) {
        const int p = tid;
        float lg[DD];
#pragma unroll
        for (int o = 0; o < DD; ++o) lg[o] = epi[p][o] + bd[o];
        float m = lg[0];
#pragma unroll
        for (int o = 1; o < DD; ++o) m = fmaxf(m, lg[o]);
        float s = 0.f;
#pragma unroll
        for (int o = 0; o < DD; ++o) { lg[o] = expf(lg[o] - m); s += lg[o]; }
        float inv = 1.0f / s;
        float e[DPAD];
#pragma unroll
        for (int o = 0; o < DD; ++o) e[o] = lg[o] * inv;
        e[41] = e[42] = e[43] = 0.f;
        float4* dp = reinterpret_cast<float4*>(g_depth + (pix0 + p) * DPAD);
#pragma unroll
        for (int i = 0; i < DPAD / 4; ++i)
            dp[i] = make_float4(e[4 * i], e[4 * i + 1], e[4 * i + 2], e[4 * i + 3]);
    }

#pragma unroll
    for (int i = tid; i < 2048; i += 256) {
        int p = i >> 4, cq = i & 15;
        int c = DD + 4 * cq;
        float4 v;
        v.x = epi[p][c + 0] + bd[c + 0];
        v.y = epi[p][c + 1] + bd[c + 1];
        v.z = epi[p][c + 2] + bd[c + 2];
        v.w = epi[p][c + 3] + bd[c + 3];
        reinterpret_cast<float4*>(g_ctx + (pix0 + p) * CC)[cq] = v;
    }
}

// -------------------------------------------------- 3x3 inverse via adjugate
__device__ __forceinline__ void inv3(const float* m, float* o) {
    float a = m[0], b = m[1], c = m[2];
    float d = m[3], e = m[4], f = m[5];
    float g = m[6], h = m[7], i = m[8];
    float A = (e * i - f * h);
    float B = -(d * i - f * g);
    float Cc = (d * h - e * g);
    float det = a * A + b * B + c * Cc;
    float id = 1.0f / det;
    o[0] = A * id;  o[1] = -(b * i - c * h) * id;  o[2] = (b * f - c * e) * id;
    o[3] = B * id;  o[4] = (a * i - c * g) * id;   o[5] = -(a * f - c * d) * id;
    o[6] = Cc * id; o[7] = -(a * h - b * g) * id;  o[8] = (a * e - b * d) * id;
}

// ---------------- K2: geometry + run-merged voxel scatter-add (2 replicas)
__global__ void __launch_bounds__(128) k_scatter(const float* __restrict__ rots,
                                                 const float* __restrict__ trans,
                                                 const float* __restrict__ intrins,
                                                 const float* __restrict__ post_rots,
                                                 const float* __restrict__ post_trans) {
    __shared__ int   s_rank[4][DPAD];
    __shared__ float s_w[4][DPAD];

    const int wl = threadIdx.x >> 5;
    const int gw = (blockIdx.x * 128 + threadIdx.x) >> 5;
    const int lane = threadIdx.x & 31;
    if (gw >= NPIX) return;
    const int n = gw / PPC;
    const int hw = gw - n * PPC;
    const int h = hw / FW;
    const int w = hw - h * FW;

    float PR[9], Km[9], R[9], IPR[9], IK[9], M[9];
#pragma unroll
    for (int i = 0; i < 9; ++i) {
        PR[i] = post_rots[n * 9 + i];
        Km[i] = intrins[n * 9 + i];
        R[i]  = rots[n * 9 + i];
    }
    inv3(PR, IPR);
    inv3(Km, IK);
#pragma unroll
    for (int i = 0; i < 3; ++i)
#pragma unroll
        for (int j = 0; j < 3; ++j)
            M[i * 3 + j] = R[i * 3 + 0] * IK[0 + j] + R[i * 3 + 1] * IK[3 + j] +
                           R[i * 3 + 2] * IK[6 + j];
    const float t0 = trans[n * 3 + 0], t1 = trans[n * 3 + 1], t2 = trans[n * 3 + 2];
    const float pt0 = post_trans[n * 3 + 0], pt1 = post_trans[n * 3 + 1],
                pt2 = post_trans[n * 3 + 2];

    const float xsc = (float)w * (1407.0f / 87.0f);
    const float ysc = (float)h * (511.0f / 31.0f);
    const float q0 = xsc - pt0, q1 = ysc - pt1;

    auto rankOf = [&](float dv) -> int {
        float q2 = dv - pt2;
        float r0 = IPR[0] * q0 + IPR[1] * q1 + IPR[2] * q2;
        float r1 = IPR[3] * q0 + IPR[4] * q1 + IPR[5] * q2;
        float r2 = IPR[6] * q0 + IPR[7] * q1 + IPR[8] * q2;
        float s0 = r0 * r2, s1 = r1 * r2, s2 = r2;
        float px = M[0] * s0 + M[1] * s1 + M[2] * s2 + t0;
        float py = M[3] * s0 + M[4] * s1 + M[5] * s2 + t1;
        float pz = M[6] * s0 + M[7] * s1 + M[8] * s2 + t2;
        int gx = (int)((px - BXX) / 0.8f);
        int gy = (int)((py - BYY) / 0.8f);
        int gz = (int)((pz - BZZ) / 20.0f);
        return gx + gy * 128 + gz * 16384;
    };

    s_rank[wl][lane] = rankOf(4.0f + (float)lane);
    s_w[wl][lane]    = g_depth[gw * DPAD + lane];
    if (lane < 9) {
        s_rank[wl][lane + 32] = rankOf(36.0f + (float)lane);
        s_w[wl][lane + 32]    = g_depth[gw * DPAD + 32 + lane];
    }
    __syncwarp();

    const float2 cx = reinterpret_cast<const float2*>(g_ctx + gw * CC)[lane];
    float* bev = g_bev[blockIdx.x & 1];
    float* bevc = bev + lane * 2;

    // run-merged scatter: consecutive equal ranks accumulate dw first.
    int cur = -1;
    float accw = 0.f;
#pragma unroll
    for (int b = 0; b <= DD; ++b) {
        int r = -1;
        float dw = 0.f;
        if (b < DD) {
            r = s_rank[wl][b];
            if ((unsigned)r >= (unsigned)NVOX) r = -1;
            dw = s_w[wl][b];
        }
        if (r != cur) {
            if (cur >= 0)
                red2(bevc + cur * CC, cx.x * accw, cx.y * accw);
            cur = r;
            accw = 0.f;
        }
        if (r >= 0) accw += dw;
    }
}

// ------------- K3: sum replicas, [voxel][c] -> out[c][voxel], float4
__global__ void __launch_bounds__(256) k_transpose(float* __restrict__ out) {
    __shared__ float s[CC][36];
    const int v0 = blockIdx.x * 32;
    const int t = threadIdx.x;
#pragma unroll
    for (int i = 0; i < 2; ++i) {
        int idx = t + i * 256;
        int cq = idx & 15, v = idx >> 4;
        float4 a = reinterpret_cast<const float4*>(g_bev[0])[(v0 + v) * 16 + cq];
        float4 b = reinterpret_cast<const float4*>(g_bev[1])[(v0 + v) * 16 + cq];
        s[4 * cq + 0][v] = a.x + b.x;
        s[4 * cq + 1][v] = a.y + b.y;
        s[4 * cq + 2][v] = a.z + b.z;
        s[4 * cq + 3][v] = a.w + b.w;
    }
    __syncthreads();
#pragma unroll
    for (int i = 0; i < 2; ++i) {
        int idx = t + i * 256;
        int c = idx >> 3, w = idx & 7;
        float4 val = *reinterpret_cast<const float4*>(&s[c][4 * w]);
        reinterpret_cast<float4*>(out)[c * (NVOX / 4) + (v0 >> 2) + w] = val;
    }
}

extern "C" void kernel_launch(void* const* d_in, const int* in_sizes, int n_in,
                              void* d_out, int out_size) {
    const float* x          = (const float*)d_in[0];
    const float* rots       = (const float*)d_in[1];
    const float* trans      = (const float*)d_in[2];
    const float* intrins    = (const float*)d_in[3];
    const float* post_rots  = (const float*)d_in[4];
    const float* post_trans = (const float*)d_in[5];
    const float* w_depth    = (const float*)d_in[6];
    const float* b_depth    = (const float*)d_in[7];
    float* out = (float*)d_out;

    cudaFuncSetAttribute(k_feats, cudaFuncAttributeMaxDynamicSharedMemorySize,
                         FEATS_SMEM);

    k_zero<<<2048, 256>>>();
    k_feats<<<NPIX / 128, 256, FEATS_SMEM>>>(x, w_depth, b_depth);
    k_scatter<<<NPIX / 4, 128>>>(rots, trans, intrins, post_rots, post_trans);
    k_transpose<<<NVOX / 32, 256>>>(out);
}

// round 6
// speedup vs baseline: 1.0207x; 1.0207x over previous
#include <cuda_runtime.h>
#include <cuda_bf16.h>
#include <cstdint>

#define FH 32
#define FW 88
#define PPC 2816
#define NCAM 6
#define NPIX 16896
#define DD 41
#define CC 64
#define CIN 256
#define NOUT 105
#define NOUTP 112
#define NVOX 16384
#define DPAD 44

#define BXX (-50.8f - 0.4f)
#define BYY (-50.8f - 0.4f)
#define BZZ (-10.0f)

typedef unsigned long long ull;

__device__ __align__(16) float g_depth[NPIX * DPAD];
__device__ __align__(16) float g_ctx[NPIX * CC];
__device__ __align__(16) float g_bev[NVOX * CC];

__device__ __forceinline__ ull ffma2(ull a, ull b, ull c) {
    ull d;
    asm("fma.rn.f32x2 %0, %1, %2, %3;" : "=l"(d) : "l"(a), "l"(b), "l"(c));
    return d;
}

__device__ __forceinline__ void red4(float* addr, float4 v) {
    asm volatile("red.global.add.v4.f32 [%0], {%1,%2,%3,%4};"
                 :: "l"(addr), "f"(v.x), "f"(v.y), "f"(v.z), "f"(v.w) : "memory");
}

__device__ __forceinline__ void cp8(uint32_t s, const float* g) {
    asm volatile("cp.async.ca.shared.global [%0], [%1], 8;" :: "r"(s), "l"(g));
}
__device__ __forceinline__ uint32_t s2u(const void* p) {
    return (uint32_t)__cvta_generic_to_shared(p);
}

// ---------------- probe: shifts the ncu capture slot by one launch
__global__ void k_nop() {}

// ---------------------------------------------------------------- K0: zero bev
__global__ void k_zero() {
    int i = blockIdx.x * blockDim.x + threadIdx.x;
    reinterpret_cast<float4*>(g_bev)[i] = make_float4(0.f, 0.f, 0.f, 0.f);
}

// ---------------- K1: pipelined register-blocked GEMM (FFMA2) + softmax
#define KCH 16
#define XROW 136
#define XS_BYTES (KCH * XROW * 4)
#define WS_BYTES (KCH * NOUTP * 8)
#define STAGE_BYTES (XS_BYTES + WS_BYTES)
#define EPI_STRIDE 113
#define FEATS_SMEM (128 * EPI_STRIDE * 4)

__global__ void __launch_bounds__(256) k_feats(const float* __restrict__ x,
                                               const float* __restrict__ wd,
                                               const float* __restrict__ bd) {
    extern __shared__ char smem[];
    float (*epi)[EPI_STRIDE] = reinterpret_cast<float(*)[EPI_STRIDE]>(smem);

    const int tid = threadIdx.x;
    const int pg = tid & 15;
    const int og = tid >> 4;
    const int pix0 = blockIdx.x * 128;
    const int n = pix0 / PPC;
    const int p0 = pix0 - n * PPC;
    const float* xb = x + n * CIN * PPC + p0;

    const int pc0 = pg * 8 + 2 * (pg >> 2);

    int xk[4], xc[4];
#pragma unroll
    for (int r = 0; r < 4; ++r) {
        int i = tid + 256 * r;
        xk[r] = i >> 6;
        xc[r] = i & 63;
    }
    int wk[7], wo[7];
#pragma unroll
    for (int r = 0; r < 7; ++r) {
        int i = tid + 256 * r;
        wk[r] = i / NOUTP;
        wo[r] = i - wk[r] * NOUTP;
    }

    ull acc[7][4];
#pragma unroll
    for (int o = 0; o < 7; ++o)
#pragma unroll
        for (int j = 0; j < 4; ++j) acc[o][j] = 0ULL;

    {
        char* st = smem;
#pragma unroll
        for (int r = 0; r < 4; ++r) {
            int pc = 2 * xc[r] + 2 * (xc[r] >> 4);
            cp8(s2u(st + (xk[r] * XROW + pc) * 4), xb + xk[r] * PPC + 2 * xc[r]);
        }
        float2* wsd = reinterpret_cast<float2*>(st + XS_BYTES);
#pragma unroll
        for (int r = 0; r < 7; ++r) {
            float w = (wo[r] < NOUT) ? wd[wo[r] * CIN + wk[r]] : 0.f;
            wsd[wk[r] * NOUTP + wo[r]] = make_float2(w, w);
        }
        asm volatile("cp.async.commit_group;");
        asm volatile("cp.async.wait_group 0;");
        __syncthreads();
    }

    for (int kc = 0; kc < CIN; kc += KCH) {
        char* cur = smem + ((kc >> 4) & 1) * STAGE_BYTES;
        char* nxt = smem + (~(kc >> 4) & 1) * STAGE_BYTES;
        const bool more = (kc + KCH) < CIN;

        float wv[7];
        if (more) {
            const float* xn = xb + (kc + KCH) * PPC;
#pragma unroll
            for (int r = 0; r < 4; ++r) {
                int pc = 2 * xc[r] + 2 * (xc[r] >> 4);
                cp8(s2u(nxt + (xk[r] * XROW + pc) * 4), xn + xk[r] * PPC + 2 * xc[r]);
            }
#pragma unroll
            for (int r = 0; r < 7; ++r)
                wv[r] = (wo[r] < NOUT) ? wd[wo[r] * CIN + kc + KCH + wk[r]] : 0.f;
        }

        const float* xs = reinterpret_cast<const float*>(cur);
        const float2* wsd = reinterpret_cast<const float2*>(cur + XS_BYTES);
#pragma unroll
        for (int k = 0; k < KCH; ++k) {
            ull w2[7], x2[4];
            const float* xr = xs + k * XROW + pc0;
#pragma unroll
            for (int o = 0; o < 7; ++o)
                w2[o] = *reinterpret_cast<const ull*>(&wsd[k * NOUTP + og * 7 + o]);
#pragma unroll
            for (int j = 0; j < 4; ++j)
                x2[j] = *reinterpret_cast<const ull*>(xr + 2 * j);
#pragma unroll
            for (int o = 0; o < 7; ++o)
#pragma unroll
                for (int j = 0; j < 4; ++j)
                    acc[o][j] = ffma2(w2[o], x2[j], acc[o][j]);
        }

        if (more) {
            float2* wsn = reinterpret_cast<float2*>(nxt + XS_BYTES);
#pragma unroll
            for (int r = 0; r < 7; ++r)
                wsn[wk[r] * NOUTP + wo[r]] = make_float2(wv[r], wv[r]);
        }
        asm volatile("cp.async.commit_group;");
        asm volatile("cp.async.wait_group 0;");
        __syncthreads();
    }

#pragma unroll
    for (int o = 0; o < 7; ++o) {
        int out = og * 7 + o;
        if (out < NOUT) {
#pragma unroll
            for (int j = 0; j < 4; ++j) {
                float2 f = *reinterpret_cast<float2*>(&acc[o][j]);
                int p = pg * 8 + 2 * j;
                epi[p][out] = f.x;
                epi[p + 1][out] = f.y;
            }
        }
    }
    __syncthreads();

    if (tid < 128) {
        const int p = tid;
        float lg[DD];
#pragma unroll
        for (int o = 0; o < DD; ++o) lg[o] = epi[p][o] + bd[o];
        float m = lg[0];
#pragma unroll
        for (int o = 1; o < DD; ++o) m = fmaxf(m, lg[o]);
        float s = 0.f;
#pragma unroll
        for (int o = 0; o < DD; ++o) { lg[o] = expf(lg[o] - m); s += lg[o]; }
        float inv = 1.0f / s;
        float e[DPAD];
#pragma unroll
        for (int o = 0; o < DD; ++o) e[o] = lg[o] * inv;
        e[41] = e[42] = e[43] = 0.f;
        float4* dp = reinterpret_cast<float4*>(g_depth + (pix0 + p) * DPAD);
#pragma unroll
        for (int i = 0; i < DPAD / 4; ++i)
            dp[i] = make_float4(e[4 * i], e[4 * i + 1], e[4 * i + 2], e[4 * i + 3]);
    }

#pragma unroll
    for (int i = tid; i < 2048; i += 256) {
        int p = i >> 4, cq = i & 15;
        int c = DD + 4 * cq;
        float4 v;
        v.x = epi[p][c + 0] + bd[c + 0];
        v.y = epi[p][c + 1] + bd[c + 1];
        v.z = epi[p][c + 2] + bd[c + 2];
        v.w = epi[p][c + 3] + bd[c + 3];
        reinterpret_cast<float4*>(g_ctx + (pix0 + p) * CC)[cq] = v;
    }
}

// -------------------------------------------------- 3x3 inverse via adjugate
__device__ __forceinline__ void inv3(const float* m, float* o) {
    float a = m[0], b = m[1], c = m[2];
    float d = m[3], e = m[4], f = m[5];
    float g = m[6], h = m[7], i = m[8];
    float A = (e * i - f * h);
    float B = -(d * i - f * g);
    float Cc = (d * h - e * g);
    float det = a * A + b * B + c * Cc;
    float id = 1.0f / det;
    o[0] = A * id;  o[1] = -(b * i - c * h) * id;  o[2] = (b * f - c * e) * id;
    o[3] = B * id;  o[4] = (a * i - c * g) * id;   o[5] = -(a * f - c * d) * id;
    o[6] = Cc * id; o[7] = -(a * h - b * g) * id;  o[8] = (a * e - b * d) * id;
}

// ---------------- K2: geometry + pair-merged half-warp red4 scatter
__global__ void __launch_bounds__(128) k_scatter(const float* __restrict__ rots,
                                                 const float* __restrict__ trans,
                                                 const float* __restrict__ intrins,
                                                 const float* __restrict__ post_rots,
                                                 const float* __restrict__ post_trans) {
    __shared__ int   s_rank[4][DPAD];
    __shared__ float s_w[4][DPAD];

    const int wl = threadIdx.x >> 5;
    const int gw = (blockIdx.x * 128 + threadIdx.x) >> 5;
    const int lane = threadIdx.x & 31;
    if (gw >= NPIX) return;
    const int n = gw / PPC;
    const int hw = gw - n * PPC;
    const int h = hw / FW;
    const int w = hw - h * FW;

    float PR[9], Km[9], R[9], IPR[9], IK[9], M[9];
#pragma unroll
    for (int i = 0; i < 9; ++i) {
        PR[i] = post_rots[n * 9 + i];
        Km[i] = intrins[n * 9 + i];
        R[i]  = rots[n * 9 + i];
    }
    inv3(PR, IPR);
    inv3(Km, IK);
#pragma unroll
    for (int i = 0; i < 3; ++i)
#pragma unroll
        for (int j = 0; j < 3; ++j)
            M[i * 3 + j] = R[i * 3 + 0] * IK[0 + j] + R[i * 3 + 1] * IK[3 + j] +
                           R[i * 3 + 2] * IK[6 + j];
    const float t0 = trans[n * 3 + 0], t1 = trans[n * 3 + 1], t2 = trans[n * 3 + 2];
    const float pt0 = post_trans[n * 3 + 0], pt1 = post_trans[n * 3 + 1],
                pt2 = post_trans[n * 3 + 2];

    const float xsc = (float)w * (1407.0f / 87.0f);
    const float ysc = (float)h * (511.0f / 31.0f);
    const float q0 = xsc - pt0, q1 = ysc - pt1;

    auto rankOf = [&](float dv) -> int {
        float q2 = dv - pt2;
        float r0 = IPR[0] * q0 + IPR[1] * q1 + IPR[2] * q2;
        float r1 = IPR[3] * q0 + IPR[4] * q1 + IPR[5] * q2;
        float r2 = IPR[6] * q0 + IPR[7] * q1 + IPR[8] * q2;
        float s0 = r0 * r2, s1 = r1 * r2, s2 = r2;
        float px = M[0] * s0 + M[1] * s1 + M[2] * s2 + t0;
        float py = M[3] * s0 + M[4] * s1 + M[5] * s2 + t1;
        float pz = M[6] * s0 + M[7] * s1 + M[8] * s2 + t2;
        int gx = (int)((px - BXX) / 0.8f);
        int gy = (int)((py - BYY) / 0.8f);
        int gz = (int)((pz - BZZ) / 20.0f);
        return gx + gy * 128 + gz * 16384;
    };

    s_rank[wl][lane] = rankOf(4.0f + (float)lane);
    s_w[wl][lane]    = g_depth[gw * DPAD + lane];
    if (lane < 12) {
        s_rank[wl][lane + 32] = (lane < 9) ? rankOf(36.0f + (float)lane) : -1;
        s_w[wl][lane + 32]    = g_depth[gw * DPAD + 32 + lane];
    }
    __syncwarp();

    const int cl = lane & 15;
    const int half = lane >> 4;
    const float4 cx = reinterpret_cast<const float4*>(g_ctx + gw * CC)[cl];
    float* bevc = g_bev + cl * 4;

#pragma unroll
    for (int it = 0; it < 21; ++it) {
        int r0 = s_rank[wl][2 * it];
        int r1 = s_rank[wl][2 * it + 1];
        float w0 = s_w[wl][2 * it];
        float w1 = s_w[wl][2 * it + 1];
        bool v0 = (unsigned)r0 < (unsigned)NVOX;
        bool v1 = (unsigned)r1 < (unsigned)NVOX;
        if (v0 && v1 && r0 == r1) {
            // merged: single half-warp red4 with summed weight
            if (half == 0) {
                float dw = w0 + w1;
                red4(bevc + r0 * CC,
                     make_float4(cx.x * dw, cx.y * dw, cx.z * dw, cx.w * dw));
            }
        } else {
            int r = half ? r1 : r0;
            float dw = half ? w1 : w0;
            if ((unsigned)r < (unsigned)NVOX)
                red4(bevc + r * CC,
                     make_float4(cx.x * dw, cx.y * dw, cx.z * dw, cx.w * dw));
        }
    }
}

// ------------- K3: [voxel][c] -> out[c][voxel], 64 voxels/CTA, float4
__global__ void __launch_bounds__(256) k_transpose(float* __restrict__ out) {
    __shared__ float s[CC][68];
    const int v0 = blockIdx.x * 64;
    const int t = threadIdx.x;
#pragma unroll
    for (int i = 0; i < 4; ++i) {
        int idx = t + i * 256;              // 0..1023
        int cq = idx & 15, v = idx >> 4;    // v 0..63
        float4 val = reinterpret_cast<const float4*>(g_bev)[(v0 + v) * 16 + cq];
        s[4 * cq + 0][v] = val.x;
        s[4 * cq + 1][v] = val.y;
        s[4 * cq + 2][v] = val.z;
        s[4 * cq + 3][v] = val.w;
    }
    __syncthreads();
#pragma unroll
    for (int i = 0; i < 4; ++i) {
        int idx = t + i * 256;
        int c = idx >> 4, wv = idx & 15;    // 16 float4 per channel row
        float4 val = *reinterpret_cast<const float4*>(&s[c][4 * wv]);
        reinterpret_cast<float4*>(out)[c * (NVOX / 4) + (v0 >> 2) + wv] = val;
    }
}

extern "C" void kernel_launch(void* const* d_in, const int* in_sizes, int n_in,
                              void* d_out, int out_size) {
    const float* x          = (const float*)d_in[0];
    const float* rots       = (const float*)d_in[1];
    const float* trans      = (const float*)d_in[2];
    const float* intrins    = (const float*)d_in[3];
    const float* post_rots  = (const float*)d_in[4];
    const float* post_trans = (const float*)d_in[5];
    const float* w_depth    = (const float*)d_in[6];
    const float* b_depth    = (const float*)d_in[7];
    float* out = (float*)d_out;

    cudaFuncSetAttribute(k_feats, cudaFuncAttributeMaxDynamicSharedMemorySize,
                         FEATS_SMEM);

    k_nop<<<1, 32>>>();   // shifts ncu capture slot -> expect k_scatter profile
    k_zero<<<1024, 256>>>();
    k_feats<<<NPIX / 128, 256, FEATS_SMEM>>>(x, w_depth, b_depth);
    k_scatter<<<NPIX / 4, 128>>>(rots, trans, intrins, post_rots, post_trans);
    k_transpose<<<NVOX / 64, 256>>>(out);
}

// round 8
// speedup vs baseline: 1.7628x; 1.7271x over previous
#include <cuda_runtime.h>
#include <cuda_bf16.h>
#include <cstdint>

#define FH 32
#define FW 88
#define PPC 2816
#define NCAM 6
#define NPIX 16896
#define DD 41
#define CC 64
#define CIN 256
#define NOUT 105
#define NVOX 16384
#define DPAD 44

#define BXX (-50.8f - 0.4f)
#define BYY (-50.8f - 0.4f)
#define BZZ (-10.0f)

typedef unsigned long long ull;

__device__ __align__(16) float g_depth[NPIX * DPAD];
__device__ __align__(16) float g_ctx[NPIX * CC];
__device__ __align__(16) float g_bev[NVOX * CC];
__device__ float g_geo[NCAM][24];   // IPR[0:9], M[9:18], t[18:21], pt[21:24]

// ---------------------------------------------------------------- helpers
__device__ __forceinline__ void red4(float* addr, float4 v) {
    asm volatile("red.global.add.v4.f32 [%0], {%1,%2,%3,%4};"
                 :: "l"(addr), "f"(v.x), "f"(v.y), "f"(v.z), "f"(v.w) : "memory");
}
__device__ __forceinline__ uint32_t s2u(const void* p) {
    return (uint32_t)__cvta_generic_to_shared(p);
}
__device__ __forceinline__ uint32_t bfpack(float hi, float lo) {
    uint32_t d;
    asm("cvt.rn.bf16x2.f32 %0, %1, %2;" : "=r"(d) : "f"(hi), "f"(lo));
    return d;
}
__device__ __forceinline__ void ldsm4(uint32_t r[4], uint32_t addr) {
    asm volatile("ldmatrix.sync.aligned.m8n8.x4.shared.b16 {%0,%1,%2,%3}, [%4];"
                 : "=r"(r[0]), "=r"(r[1]), "=r"(r[2]), "=r"(r[3]) : "r"(addr));
}
__device__ __forceinline__ void ldsm2t(uint32_t r[2], uint32_t addr) {
    asm volatile("ldmatrix.sync.aligned.m8n8.x2.trans.shared.b16 {%0,%1}, [%2];"
                 : "=r"(r[0]), "=r"(r[1]) : "r"(addr));
}
__device__ __forceinline__ void mma16816(float d[4], const uint32_t a[4],
                                         const uint32_t b[2]) {
    asm volatile(
        "mma.sync.aligned.m16n8k16.row.col.f32.bf16.bf16.f32 "
        "{%0,%1,%2,%3}, {%4,%5,%6,%7}, {%8,%9}, {%0,%1,%2,%3};"
        : "+f"(d[0]), "+f"(d[1]), "+f"(d[2]), "+f"(d[3])
        : "r"(a[0]), "r"(a[1]), "r"(a[2]), "r"(a[3]), "r"(b[0]), "r"(b[1]));
}

__global__ void k_nop() {}

// ---------------------------------------------------------------- K0: zero bev
__global__ void k_zero() {
    int i = blockIdx.x * blockDim.x + threadIdx.x;
    reinterpret_cast<float4*>(g_bev)[i] = make_float4(0.f, 0.f, 0.f, 0.f);
}

// -------------------------------------------------- 3x3 inverse via adjugate
__device__ __forceinline__ void inv3(const float* m, float* o) {
    float a = m[0], b = m[1], c = m[2];
    float d = m[3], e = m[4], f = m[5];
    float g = m[6], h = m[7], i = m[8];
    float A = (e * i - f * h);
    float B = -(d * i - f * g);
    float Cc = (d * h - e * g);
    float det = a * A + b * B + c * Cc;
    float id = 1.0f / det;
    o[0] = A * id;  o[1] = -(b * i - c * h) * id;  o[2] = (b * f - c * e) * id;
    o[3] = B * id;  o[4] = (a * i - c * g) * id;   o[5] = -(a * f - c * d) * id;
    o[6] = Cc * id; o[7] = -(a * h - b * g) * id;  o[8] = (a * e - b * d) * id;
}

// ------------------------------------------- K-1: per-camera geometry constants
__global__ void k_geo(const float* __restrict__ rots,
                      const float* __restrict__ trans,
                      const float* __restrict__ intrins,
                      const float* __restrict__ post_rots,
                      const float* __restrict__ post_trans) {
    int n = threadIdx.x;
    if (n >= NCAM) return;
    float PR[9], Km[9], R[9], IPR[9], IK[9], M[9];
#pragma unroll
    for (int i = 0; i < 9; ++i) {
        PR[i] = post_rots[n * 9 + i];
        Km[i] = intrins[n * 9 + i];
        R[i]  = rots[n * 9 + i];
    }
    inv3(PR, IPR);
    inv3(Km, IK);
#pragma unroll
    for (int i = 0; i < 3; ++i)
#pragma unroll
        for (int j = 0; j < 3; ++j)
            M[i * 3 + j] = R[i * 3 + 0] * IK[0 + j] + R[i * 3 + 1] * IK[3 + j] +
                           R[i * 3 + 2] * IK[6 + j];
    float* G = g_geo[n];
#pragma unroll
    for (int i = 0; i < 9; ++i) { G[i] = IPR[i]; G[9 + i] = M[i]; }
#pragma unroll
    for (int i = 0; i < 3; ++i) {
        G[18 + i] = trans[n * 3 + i];
        G[21 + i] = post_trans[n * 3 + i];
    }
}

// ============== K1: bf16-split HMMA GEMM (mma.sync.m16n8k16) + softmax =======
// CTA 256 thr (8 warps). Warp w<7: 16 outputs x 128 px. K chunks of 64.
// smem tiles: w[112][64] hi/lo (swizzled 128B rows), x[64][128] hi/lo (256B rows).
#define KC 64
#define WH_OFF 0
#define WL_OFF 14336
#define XH_OFF 28672
#define XL_OFF 45056
#define EPI_S 130
#define DYN_SMEM (128 * EPI_S * 4)   // 66560 (> 61440 tile bytes, overlaid)

__global__ void __launch_bounds__(256) k_feats_mma(const float* __restrict__ x,
                                                   const float* __restrict__ wd,
                                                   const float* __restrict__ bd) {
    extern __shared__ char smem[];
    const uint32_t su = s2u(smem);
    float (*epi)[EPI_S] = reinterpret_cast<float(*)[EPI_S]>(smem);

    const int tid = threadIdx.x;
    const int wid = tid >> 5;
    const int lane = tid & 31;
    const int m0 = wid * 16;

    const int pix0 = blockIdx.x * 128;
    const int n = pix0 / PPC;
    const int p0 = pix0 - n * PPC;
    const float* xb = x + n * CIN * PPC + p0;

    float acc[16][4];
#pragma unroll
    for (int t = 0; t < 16; ++t)
#pragma unroll
        for (int j = 0; j < 4; ++j) acc[t][j] = 0.f;

    // per-thread fill coordinates (chunk-invariant)
    const int wm = (tid * 7) >> 4;          // placeholder avoided below
    (void)wm;
    float4 wpre[7], xpre[8];

    auto load_regs = [&](int c) {
        const int kc = c * KC;
#pragma unroll
        for (int r = 0; r < 7; ++r) {
            int i = tid + 256 * r;          // 0..1791
            int m = i >> 4, kq = i & 15;
            wpre[r] = (m < NOUT)
                ? *reinterpret_cast<const float4*>(wd + m * CIN + kc + 4 * kq)
                : make_float4(0.f, 0.f, 0.f, 0.f);
        }
#pragma unroll
        for (int r = 0; r < 8; ++r) {
            int i = tid + 256 * r;          // 0..2047
            int k = i >> 5, pq = i & 31;
            xpre[r] = *reinterpret_cast<const float4*>(xb + (kc + k) * PPC + 4 * pq);
        }
    };

    auto fill_sts = [&]() {
#pragma unroll
        for (int r = 0; r < 7; ++r) {
            int i = tid + 256 * r;
            int m = i >> 4, kq = i & 15;
            float4 v = wpre[r];
            uint32_t h01 = bfpack(v.y, v.x);
            uint32_t h23 = bfpack(v.w, v.z);
            float f0 = __uint_as_float(h01 << 16);
            float f1 = __uint_as_float(h01 & 0xFFFF0000u);
            float f2 = __uint_as_float(h23 << 16);
            float f3 = __uint_as_float(h23 & 0xFFFF0000u);
            uint32_t l01 = bfpack(v.y - f1, v.x - f0);
            uint32_t l23 = bfpack(v.w - f3, v.z - f2);
            uint32_t off = (uint32_t)(m * 128 + ((kq * 8) ^ ((m & 7) << 4)));
            *reinterpret_cast<uint2*>(smem + WH_OFF + off) = make_uint2(h01, h23);
            *reinterpret_cast<uint2*>(smem + WL_OFF + off) = make_uint2(l01, l23);
        }
#pragma unroll
        for (int r = 0; r < 8; ++r) {
            int i = tid + 256 * r;
            int k = i >> 5, pq = i & 31;
            float4 v = xpre[r];
            uint32_t h01 = bfpack(v.y, v.x);
            uint32_t h23 = bfpack(v.w, v.z);
            float f0 = __uint_as_float(h01 << 16);
            float f1 = __uint_as_float(h01 & 0xFFFF0000u);
            float f2 = __uint_as_float(h23 << 16);
            float f3 = __uint_as_float(h23 & 0xFFFF0000u);
            uint32_t l01 = bfpack(v.y - f1, v.x - f0);
            uint32_t l23 = bfpack(v.w - f3, v.z - f2);
            uint32_t off = (uint32_t)(k * 256 + ((pq * 8) ^ ((k & 7) << 4)));
            *reinterpret_cast<uint2*>(smem + XH_OFF + off) = make_uint2(h01, h23);
            *reinterpret_cast<uint2*>(smem + XL_OFF + off) = make_uint2(l01, l23);
        }
    };

    // A/B ldmatrix address pieces
    const int mat = lane >> 3, r8 = lane & 7;
    const uint32_t a_row = (uint32_t)(m0 + (mat & 1) * 8 + r8);
    const uint32_t km16 = (uint32_t)((mat >> 1) * 16);
    const uint32_t rx = (uint32_t)(r8 << 4);
    const uint32_t bkr = (uint32_t)(lane & 15);
    const uint32_t bx = (uint32_t)((lane & 7) << 4);

    load_regs(0);
    for (int c = 0; c < 4; ++c) {
        fill_sts();
        __syncthreads();
        if (c < 3) load_regs(c + 1);   // LDG latency hides under MMA below

        if (wid < 7) {
#pragma unroll
            for (int kt = 0; kt < 4; ++kt) {
                uint32_t ah[4], al[4];
                uint32_t aoff = a_row * 128 + (((uint32_t)(kt * 32) + km16) ^ rx);
                ldsm4(ah, su + WH_OFF + aoff);
                ldsm4(al, su + WL_OFF + aoff);
                uint32_t brow = ((uint32_t)(kt * 16) + bkr) * 256;
#pragma unroll
                for (int nt = 0; nt < 16; ++nt) {
                    uint32_t bh[2], bl[2];
                    uint32_t boff = brow + (((uint32_t)(nt * 16)) ^ bx);
                    ldsm2t(bh, su + XH_OFF + boff);
                    ldsm2t(bl, su + XL_OFF + boff);
                    mma16816(acc[nt], ah, bh);   // hi*hi
                    mma16816(acc[nt], al, bh);   // lo*hi
                    mma16816(acc[nt], ah, bl);   // hi*lo
                }
            }
        }
        __syncthreads();
    }

    // ---- write accumulators into epi[out][pix] (overlays tiles)
    if (wid < 7) {
        const int g = lane >> 2, tg = lane & 3;
#pragma unroll
        for (int nt = 0; nt < 16; ++nt) {
            int px = nt * 8 + tg * 2;
            *reinterpret_cast<float2*>(&epi[m0 + g][px]) =
                make_float2(acc[nt][0], acc[nt][1]);
            *reinterpret_cast<float2*>(&epi[m0 + g + 8][px]) =
                make_float2(acc[nt][2], acc[nt][3]);
        }
    }
    __syncthreads();

    // softmax: one thread per pixel
    if (tid < 128) {
        const int p = tid;
        float lg[DD];
#pragma unroll
        for (int o = 0; o < DD; ++o) lg[o] = epi[o][p] + bd[o];
        float m = lg[0];
#pragma unroll
        for (int o = 1; o < DD; ++o) m = fmaxf(m, lg[o]);
        float sum = 0.f;
#pragma unroll
        for (int o = 0; o < DD; ++o) { lg[o] = expf(lg[o] - m); sum += lg[o]; }
        float inv = 1.0f / sum;
        float e[DPAD];
#pragma unroll
        for (int o = 0; o < DD; ++o) e[o] = lg[o] * inv;
        e[41] = e[42] = e[43] = 0.f;
        float4* dp = reinterpret_cast<float4*>(g_depth + (pix0 + p) * DPAD);
#pragma unroll
        for (int i = 0; i < DPAD / 4; ++i)
            dp[i] = make_float4(e[4 * i], e[4 * i + 1], e[4 * i + 2], e[4 * i + 3]);
    }

    // ctx
#pragma unroll
    for (int i = tid; i < 2048; i += 256) {
        int p = i >> 4, cq = i & 15;
        int cb = DD + 4 * cq;
        float4 v;
        v.x = epi[cb + 0][p] + bd[cb + 0];
        v.y = epi[cb + 1][p] + bd[cb + 1];
        v.z = epi[cb + 2][p] + bd[cb + 2];
        v.w = epi[cb + 3][p] + bd[cb + 3];
        reinterpret_cast<float4*>(g_ctx + (pix0 + p) * CC)[cq] = v;
    }
}

// ---------------- K2: geometry (precomputed) + half-warp red4 scatter
__global__ void __launch_bounds__(128) k_scatter() {
    __shared__ int   s_rank[4][DPAD];
    __shared__ float s_w[4][DPAD];

    const int wl = threadIdx.x >> 5;
    const int gw = (blockIdx.x * 128 + threadIdx.x) >> 5;
    const int lane = threadIdx.x & 31;
    if (gw >= NPIX) return;
    const int n = gw / PPC;
    const int hw = gw - n * PPC;
    const int h = hw / FW;
    const int w = hw - h * FW;

    const float* G = g_geo[n];
    float IPR[9], M[9];
#pragma unroll
    for (int i = 0; i < 9; ++i) { IPR[i] = G[i]; M[i] = G[9 + i]; }
    const float t0 = G[18], t1 = G[19], t2 = G[20];
    const float pt0 = G[21], pt1 = G[22], pt2 = G[23];

    const float xsc = (float)w * (1407.0f / 87.0f);
    const float ysc = (float)h * (511.0f / 31.0f);
    const float q0 = xsc - pt0, q1 = ysc - pt1;

    auto rankOf = [&](float dv) -> int {
        float q2 = dv - pt2;
        float r0 = IPR[0] * q0 + IPR[1] * q1 + IPR[2] * q2;
        float r1 = IPR[3] * q0 + IPR[4] * q1 + IPR[5] * q2;
        float r2 = IPR[6] * q0 + IPR[7] * q1 + IPR[8] * q2;
        float s0 = r0 * r2, s1 = r1 * r2, s2 = r2;
        float px = M[0] * s0 + M[1] * s1 + M[2] * s2 + t0;
        float py = M[3] * s0 + M[4] * s1 + M[5] * s2 + t1;
        float pz = M[6] * s0 + M[7] * s1 + M[8] * s2 + t2;
        int gx = (int)((px - BXX) / 0.8f);
        int gy = (int)((py - BYY) / 0.8f);
        int gz = (int)((pz - BZZ) / 20.0f);
        return gx + gy * 128 + gz * 16384;
    };

    s_rank[wl][lane] = rankOf(4.0f + (float)lane);
    s_w[wl][lane]    = g_depth[gw * DPAD + lane];
    if (lane < 12) {
        s_rank[wl][lane + 32] = (lane < 9) ? rankOf(36.0f + (float)lane) : -1;
        s_w[wl][lane + 32]    = g_depth[gw * DPAD + 32 + lane];
    }
    __syncwarp();

    const int cl = lane & 15;
    const int half = lane >> 4;
    const float4 cx = reinterpret_cast<const float4*>(g_ctx + gw * CC)[cl];
    float* bevc = g_bev + cl * 4;

#pragma unroll
    for (int it = 0; it < 21; ++it) {
        int b = 2 * it + half;
        int rr = s_rank[wl][b];
        float dw = s_w[wl][b];
        if ((unsigned)rr < (unsigned)NVOX) {
            float4 v = make_float4(cx.x * dw, cx.y * dw, cx.z * dw, cx.w * dw);
            red4(bevc + rr * CC, v);
        }
    }
}

// ------------- K3: [voxel][c] -> out[c][voxel], 64 voxels/CTA, float4
__global__ void __launch_bounds__(256) k_transpose(float* __restrict__ out) {
    __shared__ float s[CC][68];
    const int v0 = blockIdx.x * 64;
    const int t = threadIdx.x;
#pragma unroll
    for (int i = 0; i < 4; ++i) {
        int idx = t + i * 256;
        int cq = idx & 15, v = idx >> 4;
        float4 val = reinterpret_cast<const float4*>(g_bev)[(v0 + v) * 16 + cq];
        s[4 * cq + 0][v] = val.x;
        s[4 * cq + 1][v] = val.y;
        s[4 * cq + 2][v] = val.z;
        s[4 * cq + 3][v] = val.w;
    }
    __syncthreads();
#pragma unroll
    for (int i = 0; i < 4; ++i) {
        int idx = t + i * 256;
        int c = idx >> 4, wv = idx & 15;
        float4 val = *reinterpret_cast<const float4*>(&s[c][4 * wv]);
        reinterpret_cast<float4*>(out)[c * (NVOX / 4) + (v0 >> 2) + wv] = val;
    }
}

extern "C" void kernel_launch(void* const* d_in, const int* in_sizes, int n_in,
                              void* d_out, int out_size) {
    const float* x          = (const float*)d_in[0];
    const float* rots       = (const float*)d_in[1];
    const float* trans      = (const float*)d_in[2];
    const float* intrins    = (const float*)d_in[3];
    const float* post_rots  = (const float*)d_in[4];
    const float* post_trans = (const float*)d_in[5];
    const float* w_depth    = (const float*)d_in[6];
    const float* b_depth    = (const float*)d_in[7];
    float* out = (float*)d_out;

    cudaFuncSetAttribute(k_feats_mma, cudaFuncAttributeMaxDynamicSharedMemorySize,
                         DYN_SMEM);

    k_geo<<<1, 32>>>(rots, trans, intrins, post_rots, post_trans);  // pos 1
    k_zero<<<1024, 256>>>();                                        // pos 2
    k_nop<<<1, 32>>>();                                             // pos 3
    k_feats_mma<<<NPIX / 128, 256, DYN_SMEM>>>(x, w_depth, b_depth); // pos 4 (profiled)
    k_scatter<<<NPIX / 4, 128>>>();                                 // pos 5
    k_transpose<<<NVOX / 64, 256>>>(out);                           // pos 6
}